// round 5
// baseline (speedup 1.0000x reference)
#include <cuda_runtime.h>
#include <cuda_bf16.h>
#include <math.h>

// ElevationSConvResidualEncoder — GB300 sm_103a
//
// Dead-code proof (round 0, confirmed rel_err=2e-7):
//   mem = sigmoid(o)*tanh(syn) <= 1.0 always => spike == 0 always
//   => pooled == 0 => residual == proj_b
//   => out[0] = relu(distance @ Wd^T + bd)
//      out[1] = relu(azimuth  @ Wa^T + ba)
//      out[2] = relu(relu(elev @ We^T + be) + 0.4*sigmoid(gain)*proj_b)
//
// Round-5: launch-overhead-dominated regime (~5000cy T_ovh + 1 DRAM RT + tail).
// redux.sync.add.f32 is NOT supported on sm_103a (round-4 ptxas error) —
// back to the shfl butterfly, keeping the round-4 tail improvements:
//   - tree-shaped FMA (depth 5 instead of 8)
//   - two interleaved butterflies (chains pipeline)
//   - hoisted scalar deps (bias[j], proj_b[j], gain) + __expf (direct MUFU)
// Shape: warp per (m, j, batch-pair): 6144 warps, 384 blocks x 512 thr,
// single wave. W read exactly once from DRAM (1.57 MB).

#define HID 512
#define KDIM 256
#define N_WARP (3 * HID * 4)
#define THREADS 512

__global__ __launch_bounds__(THREADS) void enc_out_kernel(
    const float* __restrict__ distance,
    const float* __restrict__ azimuth,
    const float* __restrict__ elevation,
    const float* __restrict__ Wd, const float* __restrict__ bd,
    const float* __restrict__ Wa, const float* __restrict__ ba,
    const float* __restrict__ We, const float* __restrict__ be,
    const float* __restrict__ proj_b,
    const float* __restrict__ residual_gain,
    float* __restrict__ out)
{
    const int gwarp = blockIdx.x * (THREADS / 32) + (threadIdx.x >> 5);
    const int lane  = threadIdx.x & 31;

    const int m  = gwarp >> 11;          // 0..2
    const int r  = gwarp & 2047;
    const int j  = r >> 2;               // 0..511
    const int b0 = (r & 3) * 2;          // batches b0, b0+1

    const float* x;
    const float* W;
    const float* bias;
    if (m == 0)      { x = distance;  W = Wd; bias = bd; }
    else if (m == 1) { x = azimuth;   W = Wa; bias = ba; }
    else             { x = elevation; W = We; bias = be; }

    // ---- issue ALL loads up front (single memory-latency exposure) ----
    const float4* wv  = reinterpret_cast<const float4*>(W + (size_t)j * KDIM) + lane * 2;
    const float4* xva = reinterpret_cast<const float4*>(x + (size_t)b0 * KDIM) + lane * 2;
    const float4* xvb = xva + (KDIM / 4);

    const float4 w0 = wv[0];
    const float4 w1 = wv[1];
    const float4 a0 = xva[0];
    const float4 a1 = xva[1];
    const float4 c0 = xvb[0];
    const float4 c1 = xvb[1];

    // Scalar tail dependencies, hoisted to overlap the vector-load wait.
    const float bj = bias[j];
    float addj = 0.0f;
    if (m == 2) {
        const float g = residual_gain[0];
        addj = (0.4f / (1.0f + __expf(-g))) * proj_b[j];
    }

    // ---- tree-shaped dot products (dep depth 5 instead of 8) ----
    float sa0 = a0.x * w0.x;
    float sa1 = a1.x * w1.x;
    float sb0 = c0.x * w0.x;
    float sb1 = c1.x * w1.x;
    sa0 = fmaf(a0.y, w0.y, sa0);  sa1 = fmaf(a1.y, w1.y, sa1);
    sb0 = fmaf(c0.y, w0.y, sb0);  sb1 = fmaf(c1.y, w1.y, sb1);
    sa0 = fmaf(a0.z, w0.z, sa0);  sa1 = fmaf(a1.z, w1.z, sa1);
    sb0 = fmaf(c0.z, w0.z, sb0);  sb1 = fmaf(c1.z, w1.z, sb1);
    sa0 = fmaf(a0.w, w0.w, sa0);  sa1 = fmaf(a1.w, w1.w, sa1);
    sb0 = fmaf(c0.w, w0.w, sb0);  sb1 = fmaf(c1.w, w1.w, sb1);
    float sa = sa0 + sa1;
    float sb = sb0 + sb1;

    // ---- two interleaved 5-step butterflies (chains pipeline) ----
    #pragma unroll
    for (int off = 16; off; off >>= 1) {
        const float ta = __shfl_xor_sync(0xffffffffu, sa, off);
        const float tb = __shfl_xor_sync(0xffffffffu, sb, off);
        sa += ta;
        sb += tb;
    }

    if (lane == 0) {
        float va = fmaxf(sa + bj, 0.0f);
        float vb = fmaxf(sb + bj, 0.0f);
        if (m == 2) {
            va = fmaxf(va + addj, 0.0f);
            vb = fmaxf(vb + addj, 0.0f);
        }
        float* o = out + ((size_t)m << 12) + (size_t)b0 * HID + j;
        o[0]   = va;
        o[HID] = vb;
    }
}

extern "C" void kernel_launch(void* const* d_in, const int* in_sizes, int n_in,
                              void* d_out, int out_size)
{
    // 0 distance 1 azimuth 2 elevation 3 receive_spikes 4 spike_count
    // 5 Wd 6 bd 7 Wa 8 ba 9 We 10 be 11 conv_W 12 conv_b 13 proj_W 14 proj_b
    // 15 residual_gain
    (void)in_sizes; (void)n_in; (void)out_size;
    const float* distance  = (const float*)d_in[0];
    const float* azimuth   = (const float*)d_in[1];
    const float* elevation = (const float*)d_in[2];
    const float* Wd        = (const float*)d_in[5];
    const float* bd        = (const float*)d_in[6];
    const float* Wa        = (const float*)d_in[7];
    const float* ba        = (const float*)d_in[8];
    const float* We        = (const float*)d_in[9];
    const float* be        = (const float*)d_in[10];
    const float* proj_b    = (const float*)d_in[14];
    const float* gain      = (const float*)d_in[15];
    float* out = (float*)d_out;

    const int blocks = N_WARP / (THREADS / 32);   // 384
    enc_out_kernel<<<blocks, THREADS>>>(distance, azimuth, elevation,
                                        Wd, bd, Wa, ba, We, be,
                                        proj_b, gain, out);
}

// round 6
// speedup vs baseline: 1.1298x; 1.1298x over previous
#include <cuda_runtime.h>
#include <cuda_bf16.h>
#include <math.h>

// ElevationSConvResidualEncoder — GB300 sm_103a
//
// Dead-code proof (round 0, confirmed rel_err=2e-7):
//   mem = sigmoid(o)*tanh(syn) <= 1.0 always => spike == 0 always
//   => pooled == 0 => residual == proj_b
//   => out[0] = relu(distance @ Wd^T + bd)
//      out[1] = relu(azimuth  @ Wa^T + ba)
//      out[2] = relu(relu(elev @ We^T + be) + 0.4*sigmoid(gain)*proj_b)
//
// Round-6: launch-overhead floor regime. Final tail cut:
//   - folded dual reduction: one cross-half exchange routes sa to lanes 0-15
//     and sb to lanes 16-31, then a single 4-step butterfly finishes both.
//     10 SHFL -> 6 SHFL, and the two outputs store in parallel from lanes
//     0 and 16 (no serialized lane-0 double store).
//   - tree-shaped FMA (dep depth 5), hoisted scalar deps, __expf MUFU.
// Shape: warp per (m, j, batch-pair): 6144 warps, 384 blocks x 512 thr,
// single wave. W read exactly once from DRAM (1.57 MB).

#define HID 512
#define KDIM 256
#define N_WARP (3 * HID * 4)
#define THREADS 512

__global__ __launch_bounds__(THREADS) void enc_out_kernel(
    const float* __restrict__ distance,
    const float* __restrict__ azimuth,
    const float* __restrict__ elevation,
    const float* __restrict__ Wd, const float* __restrict__ bd,
    const float* __restrict__ Wa, const float* __restrict__ ba,
    const float* __restrict__ We, const float* __restrict__ be,
    const float* __restrict__ proj_b,
    const float* __restrict__ residual_gain,
    float* __restrict__ out)
{
    const int gwarp = blockIdx.x * (THREADS / 32) + (threadIdx.x >> 5);
    const int lane  = threadIdx.x & 31;

    const int m  = gwarp >> 11;          // 0..2
    const int r  = gwarp & 2047;
    const int j  = r >> 2;               // 0..511
    const int b0 = (r & 3) * 2;          // batches b0, b0+1

    const float* x;
    const float* W;
    const float* bias;
    if (m == 0)      { x = distance;  W = Wd; bias = bd; }
    else if (m == 1) { x = azimuth;   W = Wa; bias = ba; }
    else             { x = elevation; W = We; bias = be; }

    // ---- issue ALL loads up front (single memory-latency exposure) ----
    const float4* wv  = reinterpret_cast<const float4*>(W + (size_t)j * KDIM) + lane * 2;
    const float4* xva = reinterpret_cast<const float4*>(x + (size_t)b0 * KDIM) + lane * 2;
    const float4* xvb = xva + (KDIM / 4);

    const float4 w0 = wv[0];
    const float4 w1 = wv[1];
    const float4 a0 = xva[0];
    const float4 a1 = xva[1];
    const float4 c0 = xvb[0];
    const float4 c1 = xvb[1];

    // Scalar tail dependencies, hoisted to overlap the vector-load wait.
    const float bj = bias[j];
    float addj = 0.0f;
    if (m == 2) {
        const float g = residual_gain[0];
        addj = (0.4f / (1.0f + __expf(-g))) * proj_b[j];
    }

    // ---- tree-shaped dot products (dep depth 5 instead of 8) ----
    float sa0 = a0.x * w0.x;
    float sa1 = a1.x * w1.x;
    float sb0 = c0.x * w0.x;
    float sb1 = c1.x * w1.x;
    sa0 = fmaf(a0.y, w0.y, sa0);  sa1 = fmaf(a1.y, w1.y, sa1);
    sb0 = fmaf(c0.y, w0.y, sb0);  sb1 = fmaf(c1.y, w1.y, sb1);
    sa0 = fmaf(a0.z, w0.z, sa0);  sa1 = fmaf(a1.z, w1.z, sa1);
    sb0 = fmaf(c0.z, w0.z, sb0);  sb1 = fmaf(c1.z, w1.z, sb1);
    sa0 = fmaf(a0.w, w0.w, sa0);  sa1 = fmaf(a1.w, w1.w, sa1);
    sb0 = fmaf(c0.w, w0.w, sb0);  sb1 = fmaf(c1.w, w1.w, sb1);
    const float sa = sa0 + sa1;
    const float sb = sb0 + sb1;

    // ---- folded dual reduction ----
    // Step 1: cross-half exchange. Low lanes accumulate sa-pairs, high lanes
    // accumulate sb-pairs. Then one 4-step butterfly (xor < 16 stays within
    // each half) reduces both halves independently.
    const float ta = __shfl_xor_sync(0xffffffffu, sa, 16);
    const float tb = __shfl_xor_sync(0xffffffffu, sb, 16);
    float v = (lane < 16) ? (sa + ta) : (sb + tb);
    #pragma unroll
    for (int off = 8; off; off >>= 1)
        v += __shfl_xor_sync(0xffffffffu, v, off);
    // lane 0 holds full sa sum (batch b0); lane 16 holds full sb sum (b0+1).

    if ((lane & 15) == 0) {
        float res = fmaxf(v + bj, 0.0f);
        if (m == 2) res = fmaxf(res + addj, 0.0f);
        const int b = b0 + (lane >> 4);
        out[((size_t)m << 12) + (size_t)b * HID + j] = res;
    }
}

extern "C" void kernel_launch(void* const* d_in, const int* in_sizes, int n_in,
                              void* d_out, int out_size)
{
    // 0 distance 1 azimuth 2 elevation 3 receive_spikes 4 spike_count
    // 5 Wd 6 bd 7 Wa 8 ba 9 We 10 be 11 conv_W 12 conv_b 13 proj_W 14 proj_b
    // 15 residual_gain
    (void)in_sizes; (void)n_in; (void)out_size;
    const float* distance  = (const float*)d_in[0];
    const float* azimuth   = (const float*)d_in[1];
    const float* elevation = (const float*)d_in[2];
    const float* Wd        = (const float*)d_in[5];
    const float* bd        = (const float*)d_in[6];
    const float* Wa        = (const float*)d_in[7];
    const float* ba        = (const float*)d_in[8];
    const float* We        = (const float*)d_in[9];
    const float* be        = (const float*)d_in[10];
    const float* proj_b    = (const float*)d_in[14];
    const float* gain      = (const float*)d_in[15];
    float* out = (float*)d_out;

    const int blocks = N_WARP / (THREADS / 32);   // 384
    enc_out_kernel<<<blocks, THREADS>>>(distance, azimuth, elevation,
                                        Wd, bd, Wa, ba, We, be,
                                        proj_b, gain, out);
}